// round 2
// baseline (speedup 1.0000x reference)
#include <cuda_runtime.h>
#include <math.h>

#define NUM_NODES 90000
#define NUM_EDGES 3000000
#define DIM 64
#define LAYERS 100

// ---------------- device scratch (static allocation, allowed) ----------------
__device__ float g_x0[NUM_NODES * DIM];
__device__ float g_x1[NUM_NODES * DIM];
__device__ float g_acc[NUM_NODES * DIM];
__device__ float g_dinv[NUM_NODES];
__device__ int   g_deg[NUM_NODES];
__device__ int   g_off[NUM_NODES + 1];
__device__ int   g_fill[NUM_NODES];
__device__ int   g_src[NUM_EDGES];
__device__ float g_w[NUM_EDGES];

// ---------------- preprocessing ----------------
__global__ void k_zero_deg() {
    int i = blockIdx.x * blockDim.x + threadIdx.x;
    if (i < NUM_NODES) g_deg[i] = 0;
}

__global__ void k_degree(const int* __restrict__ edge_index) {
    int e = blockIdx.x * blockDim.x + threadIdx.x;
    if (e < NUM_EDGES) {
        int c = edge_index[NUM_EDGES + e];  // col = edge_index[1]
        atomicAdd(&g_deg[c], 1);
    }
}

__global__ void k_dinv_fill() {
    int i = blockIdx.x * blockDim.x + threadIdx.x;
    if (i < NUM_NODES) {
        int d = g_deg[i];
        g_dinv[i] = (d > 0) ? rsqrtf((float)d) : 0.0f;
        g_fill[i] = 0;
    }
}

// single-block exclusive scan over g_deg -> g_off (runs once per launch, tiny)
__global__ void k_scan() {
    __shared__ int sums[1024];
    const int t = threadIdx.x;
    const int C = (NUM_NODES + 1023) / 1024;  // chunk per thread
    const int start = t * C;
    int s = 0;
    for (int i = 0; i < C; i++) {
        int idx = start + i;
        if (idx < NUM_NODES) s += g_deg[idx];
    }
    sums[t] = s;
    __syncthreads();
    int myval = s;
    for (int o = 1; o < 1024; o <<= 1) {
        int tmp = (t >= o) ? sums[t - o] : 0;
        __syncthreads();
        sums[t] += tmp;
        __syncthreads();
    }
    int run = sums[t] - myval;  // exclusive prefix of this chunk
    for (int i = 0; i < C; i++) {
        int idx = start + i;
        if (idx < NUM_NODES) {
            g_off[idx] = run;
            run += g_deg[idx];
        }
    }
    if (t == 1023) g_off[NUM_NODES] = sums[1023];
}

__global__ void k_build_csr(const int* __restrict__ edge_index) {
    int e = blockIdx.x * blockDim.x + threadIdx.x;
    if (e < NUM_EDGES) {
        int r = edge_index[e];              // row
        int c = edge_index[NUM_EDGES + e];  // col
        int p = g_off[c] + atomicAdd(&g_fill[c], 1);
        g_src[p] = r;
        g_w[p]   = g_dinv[r] * g_dinv[c];
    }
}

__global__ void k_init(const float* __restrict__ emb) {
    int i = blockIdx.x * blockDim.x + threadIdx.x;
    if (i < NUM_NODES * DIM) {
        float v = emb[i];
        g_x0[i]  = v;
        g_acc[i] = v;
    }
}

// ---------------- one LightGCN layer: warp per destination node ----------------
__global__ void __launch_bounds__(256) k_conv(int flip) {
    const float* __restrict__ xin  = flip ? g_x1 : g_x0;
    float*       __restrict__ xout = flip ? g_x0 : g_x1;

    int gw   = (blockIdx.x * blockDim.x + threadIdx.x) >> 5;  // dest node
    int lane = threadIdx.x & 31;
    if (gw >= NUM_NODES) return;

    const int beg = g_off[gw];
    const int end = g_off[gw + 1];

    const float2* __restrict__ xin2 = (const float2*)xin;
    float2 a = make_float2(0.0f, 0.0f);

#pragma unroll 4
    for (int j = beg; j < end; j++) {
        int   s = __ldg(&g_src[j]);   // broadcast across warp
        float w = __ldg(&g_w[j]);
        float2 v = __ldg(&xin2[(size_t)s * 32 + lane]);
        a.x = fmaf(w, v.x, a.x);
        a.y = fmaf(w, v.y, a.y);
    }

    size_t o = (size_t)gw * 32 + lane;
    ((float2*)xout)[o] = a;
    float2* acc2 = (float2*)g_acc;
    float2 ac = acc2[o];
    ac.x += a.x;
    ac.y += a.y;
    acc2[o] = ac;
}

__global__ void k_final(float* __restrict__ out) {
    int i = blockIdx.x * blockDim.x + threadIdx.x;
    if (i < NUM_NODES * DIM) {
        out[i] = g_acc[i] * (1.0f / (float)(LAYERS + 1));
    }
}

// ---------------- launch ----------------
extern "C" void kernel_launch(void* const* d_in, const int* in_sizes, int n_in,
                              void* d_out, int out_size) {
    const float* emb = (const float*)d_in[0];
    const int*   ei  = (const int*)d_in[1];
    float*       out = (float*)d_out;

    const int TB = 256;
    const int nb_nodes = (NUM_NODES + TB - 1) / TB;
    const int nb_edges = (NUM_EDGES + TB - 1) / TB;
    const int nb_feat  = (NUM_NODES * DIM + TB - 1) / TB;
    const int nb_conv  = (NUM_NODES * 32 + TB - 1) / TB;

    k_zero_deg<<<nb_nodes, TB>>>();
    k_degree<<<nb_edges, TB>>>(ei);
    k_dinv_fill<<<nb_nodes, TB>>>();
    k_scan<<<1, 1024>>>();
    k_build_csr<<<nb_edges, TB>>>(ei);
    k_init<<<nb_feat, TB>>>(emb);

    for (int l = 0; l < LAYERS; l++) {
        k_conv<<<nb_conv, TB>>>(l & 1);
    }

    k_final<<<nb_feat, TB>>>(out);
}

// round 6
// speedup vs baseline: 1.0757x; 1.0757x over previous
#include <cuda_runtime.h>
#include <math.h>

#define NUM_NODES 90000
#define NUM_EDGES 3000000
#define DIM 64
#define LAYERS 100
#define NBLK 352          // ceil(90000/256)

// ---------------- device scratch (static allocation, allowed) ----------------
__device__ short2   g_q0[NUM_NODES * 32];   // int16 state ping
__device__ short2   g_q1[NUM_NODES * 32];   // int16 state pong
__device__ float    g_acc[NUM_NODES * DIM];
__device__ float    g_dinv[NUM_NODES];
__device__ int      g_deg[NUM_NODES];
__device__ int      g_off[NUM_NODES + 1];
__device__ int      g_fill[NUM_NODES];
__device__ int      g_src[NUM_EDGES];
__device__ int      g_bsum[NBLK];
__device__ int      g_boff[NBLK];
__device__ unsigned g_mx[LAYERS + 2];       // ||y_l||_inf as float bits

// ---------------- preprocessing ----------------
__global__ void k_zero_deg() {
    int i = blockIdx.x * blockDim.x + threadIdx.x;
    if (i < NUM_NODES) g_deg[i] = 0;
    if (i < LAYERS + 2) g_mx[i] = 0u;
}

__global__ void k_degree(const int* __restrict__ edge_index) {
    int e = blockIdx.x * blockDim.x + threadIdx.x;
    if (e < NUM_EDGES) {
        int c = edge_index[NUM_EDGES + e];  // col = edge_index[1]
        atomicAdd(&g_deg[c], 1);
    }
}

__global__ void k_dinv_fill() {
    int i = blockIdx.x * blockDim.x + threadIdx.x;
    if (i < NUM_NODES) {
        int d = g_deg[i];
        g_dinv[i] = (d > 0) ? rsqrtf((float)d) : 0.0f;
        g_fill[i] = 0;
    }
}

// 3-phase coalesced exclusive scan of g_deg -> g_off
__global__ void k_blocksum() {
    __shared__ int sh[256];
    int t = threadIdx.x;
    int i = blockIdx.x * 256 + t;
    sh[t] = (i < NUM_NODES) ? g_deg[i] : 0;
    __syncthreads();
    for (int o = 128; o > 0; o >>= 1) {
        if (t < o) sh[t] += sh[t + o];
        __syncthreads();
    }
    if (t == 0) g_bsum[blockIdx.x] = sh[0];
}

__global__ void k_scan_bsum() {
    __shared__ int sh[512];
    int t = threadIdx.x;
    int v = (t < NBLK) ? g_bsum[t] : 0;
    sh[t] = v;
    __syncthreads();
    for (int o = 1; o < 512; o <<= 1) {
        int tmp = (t >= o) ? sh[t - o] : 0;
        __syncthreads();
        sh[t] += tmp;
        __syncthreads();
    }
    if (t < NBLK) g_boff[t] = sh[t] - v;  // exclusive
}

__global__ void k_expand() {
    __shared__ int sh[256];
    int t = threadIdx.x;
    int i = blockIdx.x * 256 + t;
    int v = (i < NUM_NODES) ? g_deg[i] : 0;
    sh[t] = v;
    __syncthreads();
    for (int o = 1; o < 256; o <<= 1) {
        int tmp = (t >= o) ? sh[t - o] : 0;
        __syncthreads();
        sh[t] += tmp;
        __syncthreads();
    }
    if (i < NUM_NODES) g_off[i] = g_boff[blockIdx.x] + sh[t] - v;
    if (i == 0) g_off[NUM_NODES] = NUM_EDGES;
}

__global__ void k_build_csr(const int* __restrict__ edge_index) {
    int e = blockIdx.x * blockDim.x + threadIdx.x;
    if (e < NUM_EDGES) {
        int r = edge_index[e];              // row
        int c = edge_index[NUM_EDGES + e];  // col
        int p = g_off[c] + atomicAdd(&g_fill[c], 1);
        g_src[p] = r;
    }
}

// pass A: g_mx[0] = max |dinv*emb|
__global__ void k_init_max(const float* __restrict__ emb) {
    __shared__ float sm[256];
    int t = threadIdx.x;
    int i = blockIdx.x * 256 + t;  // over N*32 float2 slots
    float m = 0.0f;
    if (i < NUM_NODES * 32) {
        float d = g_dinv[i >> 5];
        float2 v = ((const float2*)emb)[i];
        m = fmaxf(fabsf(d * v.x), fabsf(d * v.y));
    }
    sm[t] = m;
    __syncthreads();
    for (int o = 128; o > 0; o >>= 1) {
        if (t < o) sm[t] = fmaxf(sm[t], sm[t + o]);
        __syncthreads();
    }
    if (t == 0) atomicMax(&g_mx[0], __float_as_uint(sm[0]));
}

// pass B: acc = emb; q0 = quantize(dinv*emb, scale=g_mx[0])
__global__ void k_init_quant(const float* __restrict__ emb) {
    int i = blockIdx.x * blockDim.x + threadIdx.x;
    if (i < NUM_NODES * 32) {
        float d = g_dinv[i >> 5];
        float S = __uint_as_float(g_mx[0]);
        float enc = (S > 0.0f) ? 32767.0f / S : 0.0f;
        float2 v = ((const float2*)emb)[i];
        ((float2*)g_acc)[i] = v;
        int qx = __float2int_rn(d * v.x * enc);
        int qy = __float2int_rn(d * v.y * enc);
        qx = max(-32767, min(32767, qx));
        qy = max(-32767, min(32767, qy));
        g_q0[i] = make_short2((short)qx, (short)qy);
    }
}

// ---------------- one layer: warp per destination node ----------------
__global__ void __launch_bounds__(256) k_conv(int l, int flip) {
    const short2* __restrict__ qin  = flip ? g_q1 : g_q0;
    short2*       __restrict__ qout = flip ? g_q0 : g_q1;

    int warp = (blockIdx.x * blockDim.x + threadIdx.x) >> 5;  // dest node
    int lane = threadIdx.x & 31;
    int wid  = threadIdx.x >> 5;
    bool active = (warp < NUM_NODES);

    // y_l was encoded with g_mx[max(l-1,0)]; encode y_{l+1} with g_mx[l] (>= ||y_{l+1}||inf)
    float S_dec = __uint_as_float(g_mx[(l == 0) ? 0 : (l - 1)]);
    float S_enc = __uint_as_float(g_mx[l]);
    float dec  = S_dec * (1.0f / 32767.0f);
    float encr = (S_enc > 0.0f) ? (32767.0f / S_enc) : 0.0f;

    int beg = 0, end = 0;
    if (active) { beg = g_off[warp]; end = g_off[warp + 1]; }

    const int* __restrict__ qin32 = (const int*)qin;
    int a0 = 0, a1 = 0;

    int j = beg;
    for (; j + 32 <= end; j += 32) {
        int idx = __ldg(&g_src[j + lane]);
#pragma unroll
        for (int k = 0; k < 32; k++) {
            int s = __shfl_sync(0xffffffffu, idx, k);
            int v = __ldg(&qin32[s * 32 + lane]);
            a0 += (v << 16) >> 16;  // low short, sign-extended
            a1 += v >> 16;          // high short
        }
    }
    if (j < end) {
        int idx = (j + lane < end) ? __ldg(&g_src[j + lane]) : 0;
        int n = end - j;
#pragma unroll 4
        for (int k = 0; k < n; k++) {
            int s = __shfl_sync(0xffffffffu, idx, k);
            int v = __ldg(&qin32[s * 32 + lane]);
            a0 += (v << 16) >> 16;
            a1 += v >> 16;
        }
    }

    float m = 0.0f;
    if (active) {
        float dc = g_dinv[warp];
        // x_new = dc * dec * a  (exact integer sum, one fp scale)
        float xn0 = dc * ((float)a0 * dec);
        float xn1 = dc * ((float)a1 * dec);

        size_t o = (size_t)warp * 32 + lane;
        float2* acc2 = (float2*)g_acc;
        float2 ac = acc2[o];
        ac.x += xn0;
        ac.y += xn1;
        acc2[o] = ac;

        // y_{l+1} = dc * x_new ; quantize with S_enc
        float t0 = dc * xn0;
        float t1 = dc * xn1;
        int q0i = __float2int_rn(t0 * encr);
        int q1i = __float2int_rn(t1 * encr);
        q0i = max(-32767, min(32767, q0i));
        q1i = max(-32767, min(32767, q1i));
        qout[o] = make_short2((short)q0i, (short)q1i);

        m = fmaxf(fabsf(t0), fabsf(t1));
    }

    // block max of |t| -> g_mx[l+1]  (exact ||y_{l+1}||inf)
#pragma unroll
    for (int o = 16; o > 0; o >>= 1)
        m = fmaxf(m, __shfl_xor_sync(0xffffffffu, m, o));
    __shared__ float smax[8];
    if (lane == 0) smax[wid] = m;
    __syncthreads();
    if (threadIdx.x == 0) {
        float bm = smax[0];
#pragma unroll
        for (int k = 1; k < 8; k++) bm = fmaxf(bm, smax[k]);
        atomicMax(&g_mx[l + 1], __float_as_uint(bm));
    }
}

__global__ void k_final(float* __restrict__ out) {
    int i = blockIdx.x * blockDim.x + threadIdx.x;
    if (i < NUM_NODES * DIM) {
        out[i] = g_acc[i] * (1.0f / (float)(LAYERS + 1));
    }
}

// ---------------- launch ----------------
extern "C" void kernel_launch(void* const* d_in, const int* in_sizes, int n_in,
                              void* d_out, int out_size) {
    const float* emb = (const float*)d_in[0];
    const int*   ei  = (const int*)d_in[1];
    float*       out = (float*)d_out;

    const int TB = 256;
    const int nb_nodes = (NUM_NODES + TB - 1) / TB;
    const int nb_edges = (NUM_EDGES + TB - 1) / TB;
    const int nb_feat  = (NUM_NODES * DIM + TB - 1) / TB;
    const int nb_half  = (NUM_NODES * 32 + TB - 1) / TB;
    const int nb_conv  = (NUM_NODES * 32 + TB - 1) / TB;

    k_zero_deg<<<nb_nodes, TB>>>();
    k_degree<<<nb_edges, TB>>>(ei);
    k_dinv_fill<<<nb_nodes, TB>>>();
    k_blocksum<<<NBLK, 256>>>();
    k_scan_bsum<<<1, 512>>>();
    k_expand<<<NBLK, 256>>>();
    k_build_csr<<<nb_edges, TB>>>(ei);
    k_init_max<<<nb_half, TB>>>(emb);
    k_init_quant<<<nb_half, TB>>>(emb);

    for (int l = 0; l < LAYERS; l++) {
        k_conv<<<nb_conv, TB>>>(l, l & 1);
    }

    k_final<<<nb_feat, TB>>>(out);
}